// round 12
// baseline (speedup 1.0000x reference)
#include <cuda_runtime.h>
#include <stdint.h>

// Coarse key space: 128^3 = 2^21, key = (bx<<14)|(by<<7)|bz.
// Numeric key order == lexicographic row order of jnp.unique. No sort needed.
#define NKEYS    (1 << 21)
#define NWORDS   (NKEYS / 64)    // 32768 u64 presence words = 256 KB (L2-resident)
#define NREG     1024            // regions of 2048 keys (32 words); counts built in k_mark
#define MAXN     600000

__device__ unsigned long long g_bits[NWORDS];   // presence bitmap
__device__ unsigned           g_rcnt[NREG];     // per-region unique-key counts (built by first-setters)
__device__ unsigned           g_rank[NKEYS];    // rank per key; touched ONLY at present keys (no init)
__device__ int                g_winner[MAXN * 8]; // last-writer point idx per (rank, offset) slot

__device__ __forceinline__ unsigned pack_key(int cx, int cy, int cz) {
    return ((unsigned)(cx >> 1) << 14) | ((unsigned)(cy >> 1) << 7) | (unsigned)(cz >> 1);
}

// ---------------------------------------------------------------------------
// Init scratch: bitmap = 0 (256 KB), region counts = 0, winner = -1 (16 MB,
// int4-vectorized). ucoords fill moved into k_emit (disjoint partition).
__global__ void k_init(int n) {
    int i = blockIdx.x * blockDim.x + threadIdx.x;
    if (i < NWORDS) g_bits[i] = 0ull;
    if (i < NREG)   g_rcnt[i] = 0u;
    if (i < n * 2)  ((int4*)g_winner)[i] = make_int4(-1, -1, -1, -1);  // n*8 ints
}

// Set presence bits; atomicOr's return value identifies the FIRST setter of
// each bit, which bumps its region count. The count set is deterministic
// (one increment per present key) regardless of thread timing.
__global__ void k_mark(const int* __restrict__ coords, int n) {
    int i = blockIdx.x * blockDim.x + threadIdx.x;
    if (i >= n) return;
    int cx = coords[3 * i], cy = coords[3 * i + 1], cz = coords[3 * i + 2];
    unsigned key = pack_key(cx, cy, cz);
    unsigned long long m = 1ull << (key & 63);
    unsigned long long old = atomicOr(&g_bits[key >> 6], m);
    if (!(old & m)) atomicAdd(&g_rcnt[key >> 11], 1u);
}

// One block per region (1024 blocks) + fill partition.
//  Region block b: warp 0 sums g_rcnt[0..b) (warp-parallel, L2-resident) for
//  the region's global base and warp-scans its 32 word popcounts; then the
//  256 threads emit rank + sorted unique coarse coords AS FLOATS for the
//  region's 2048 keys (8 keys/thread), writing g_rank for k_winner.
//  Fill block: computes U = sum of all region counts, writes -1.0f to rows in
//  [U, n). Row sets are disjoint across partitions — no ordering needed.
__global__ void k_emit(float* __restrict__ ucoords, int n) {
    __shared__ unsigned long long s_word[32];
    __shared__ unsigned s_wpfx[32];
    __shared__ unsigned s_base;
    int b = blockIdx.x, t = threadIdx.x;

    if (b < NREG) {
        if (t < 32) {
            unsigned long long w = g_bits[b * 32 + t];
            s_word[t] = w;
            unsigned c = (unsigned)__popcll(w);
            unsigned incl = c;
            #pragma unroll
            for (int o = 1; o < 32; o <<= 1) {
                unsigned x = __shfl_up_sync(0xFFFFFFFFu, incl, o);
                if (t >= o) incl += x;
            }
            s_wpfx[t] = incl - c;                 // exclusive word prefix in region
            unsigned acc = 0;
            for (int j = t; j < b; j += 32) acc += g_rcnt[j];
            #pragma unroll
            for (int o = 16; o > 0; o >>= 1) acc += __shfl_down_sync(0xFFFFFFFFu, acc, o);
            if (t == 0) s_base = acc;             // global rank base of region
        }
        __syncthreads();

        unsigned long long word = s_word[t >> 3];
        int bitbase = (t & 7) * 8;                // this thread owns 8 bits of its word
        unsigned r = s_base + s_wpfx[t >> 3] +
                     (unsigned)__popcll(word & ((1ull << bitbase) - 1ull));
        unsigned keybase = (unsigned)b * 2048 + (unsigned)t * 8;
        #pragma unroll
        for (int j = 0; j < 8; j++) {
            if ((word >> (bitbase + j)) & 1ull) {
                unsigned key = keybase + j;
                g_rank[key] = r;
                ucoords[3 * r]     = (float)(key >> 14);
                ucoords[3 * r + 1] = (float)((key >> 7) & 127u);
                ucoords[3 * r + 2] = (float)(key & 127u);
                r++;
            }
        }
    } else {
        if (t < 32) {
            unsigned acc = 0;
            for (int j = t; j < NREG; j += 32) acc += g_rcnt[j];
            #pragma unroll
            for (int o = 16; o > 0; o >>= 1) acc += __shfl_down_sync(0xFFFFFFFFu, acc, o);
            if (t == 0) s_base = acc;             // U = total unique count
        }
        __syncthreads();
        unsigned U = s_base;
        int row = (b - NREG) * 256 + t;           // one thread per output row
        if (row < n && (unsigned)row >= U) {
            ucoords[3 * row]     = -1.0f;
            ucoords[3 * row + 1] = -1.0f;
            ucoords[3 * row + 2] = -1.0f;
        }
    }
}

// Last-index-wins arbitration per (rank, offset) slot — deterministic match of
// the reference's sequential scatter semantics. Single cheap g_rank load.
__global__ void k_winner(const int* __restrict__ coords, int n) {
    int i = blockIdx.x * blockDim.x + threadIdx.x;
    if (i >= n) return;
    int cx = coords[3 * i], cy = coords[3 * i + 1], cz = coords[3 * i + 2];
    unsigned rank = g_rank[pack_key(cx, cy, cz)];
    int off = ((cx & 1) << 2) | ((cy & 1) << 1) | (cz & 1);
    atomicMax(&g_winner[rank * 8 + off], i);
}

// Row writer: one warp per output row (128 floats = 32 float4). Lane L owns
// float4 #L: slot = L>>2, quarter = L&3; lanes of a slot read a contiguous
// 64B feats segment. Every agg byte written exactly once, streamed with .cs
// (never re-read — keep L2 for the bitmap/rank/winner structures).
__global__ void k_rows(const float* __restrict__ feats,
                       float4* __restrict__ agg4, int n) {
    int warp = (blockIdx.x * blockDim.x + threadIdx.x) >> 5;
    int lane = threadIdx.x & 31;
    if (warp >= n) return;
    int slot = lane >> 2, q = lane & 3;
    int w = g_winner[warp * 8 + slot];
    float4 f = make_float4(0.f, 0.f, 0.f, 0.f);
    if (w >= 0) f = __ldg(&((const float4*)feats)[(size_t)w * 4 + q]);
    __stcs(&agg4[(size_t)warp * 32 + lane], f);
}

// Scalar fallback if agg isn't 16B-aligned (defensive; not expected).
__global__ void k_rows_scalar(const float* __restrict__ feats,
                              float* __restrict__ agg, int n) {
    long long g = (long long)blockIdx.x * blockDim.x + threadIdx.x;
    long long total = (long long)n * 128;
    if (g >= total) return;
    int r = (int)(g >> 7), c = (int)(g & 127);
    int w = g_winner[r * 8 + (c >> 4)];
    agg[g] = (w >= 0) ? feats[(size_t)w * 16 + (c & 15)] : 0.f;
}

// ---------------------------------------------------------------------------
extern "C" void kernel_launch(void* const* d_in, const int* in_sizes, int n_in,
                              void* d_out, int out_size) {
    // metadata order: feats (N*16 f32), coords (N*3 i32). Defensive swap check.
    int fi = 0, ci = 1;
    if (in_sizes[0] < in_sizes[1]) { fi = 1; ci = 0; }
    const float* feats  = (const float*)d_in[fi];
    const int*   coords = (const int*)d_in[ci];
    int n = in_sizes[ci] / 3;

    float* ucoords = (float*)d_out;                     // [n,3]  unique coarse coords AS FLOAT
    float* agg     = (float*)d_out + (size_t)n * 3;     // [n,128] aggregated features

    int initN = n * 2;                                   // n*2 int4s dominates (> NWORDS, NREG)
    if (NWORDS > initN) initN = NWORDS;

    k_init  <<<(initN + 255) / 256, 256>>>(n);
    k_mark  <<<(n + 255) / 256, 256>>>(coords, n);
    k_emit  <<<NREG + (n + 255) / 256, 256>>>(ucoords, n);
    k_winner<<<(n + 255) / 256, 256>>>(coords, n);

    if ((((uintptr_t)agg) & 15) == 0) {
        k_rows<<<(n + 7) / 8, 256>>>(feats, (float4*)agg, n);   // 1 warp/row, 8 rows/block
    } else {
        long long total = (long long)n * 128;
        k_rows_scalar<<<(unsigned)((total + 255) / 256), 256>>>(feats, agg, n);
    }
}